// round 1
// baseline (speedup 1.0000x reference)
#include <cuda_runtime.h>
#include <math.h>

#define BATCH 2
#define SEQ   2048
#define NH    64
#define HD    64
#define DS    128
#define CSZ   256
#define NCH   (SEQ / CSZ)   // 8

// ---------------- scratch (static device globals; no allocation) -------------
__device__ float g_dtsp[(size_t)BATCH*NH*NCH*CSZ];     // softplus(dt+bias)   (b,h,c,s)
__device__ float g_dacs[(size_t)BATCH*NH*NCH*CSZ];     // cumsum(dA)          (b,h,c,s)
__device__ float g_dAlast[(size_t)BATCH*NH*NCH];       // dacs at s=255       (b,h,c)
__device__ float g_states[(size_t)BATCH*NCH*NH*HD*DS]; // per-chunk states    (b,c,h,p,n)
__device__ float g_prev[(size_t)BATCH*NCH*NH*HD*DS];   // propagated states   (b,c,h,p,n)
__device__ float g_CB[(size_t)BATCH*NCH*CSZ*CSZ];      // C·B^T (head-indep)  (b,c,l,s)

// ---------------- K1: dt softplus + per-chunk inclusive scan -----------------
__global__ void k_dt(const float* __restrict__ dt, const float* __restrict__ A,
                     const float* __restrict__ dtb) {
    int bid = blockIdx.x;
    int c = bid % NCH;
    int h = (bid / NCH) % NH;
    int b = bid / (NCH * NH);
    int s = threadIdx.x;

    float raw = dt[((size_t)b*SEQ + c*CSZ + s)*NH + h] + dtb[h];
    // stable softplus (matches jax.nn.softplus)
    float sp = fmaxf(raw, 0.f) + log1pf(expf(-fabsf(raw)));
    float da = sp * A[h];

    int lane = s & 31, wid = s >> 5;
    float v = da;
    #pragma unroll
    for (int o = 1; o < 32; o <<= 1) {
        float t = __shfl_up_sync(0xffffffffu, v, o);
        if (lane >= o) v += t;
    }
    __shared__ float wsum[8];
    if (lane == 31) wsum[wid] = v;
    __syncthreads();
    if (s < 8) {
        float w = wsum[s];
        #pragma unroll
        for (int o = 1; o < 8; o <<= 1) {
            float t = __shfl_up_sync(0xffu, w, o);
            if (s >= o) w += t;
        }
        wsum[s] = w;
    }
    __syncthreads();
    float scan = v + (wid > 0 ? wsum[wid - 1] : 0.f);

    size_t idx = (((size_t)b*NH + h)*NCH + c)*CSZ + s;
    g_dtsp[idx] = sp;
    g_dacs[idx] = scan;
    if (s == CSZ - 1) g_dAlast[((size_t)b*NH + h)*NCH + c] = scan;
}

// ---------------- K2: chunk_state  states[p,n] = sum_s w[s]*x[s,p]*B[s,n] ----
__global__ void k_state(const float* __restrict__ x, const float* __restrict__ Bm) {
    int h = blockIdx.x, c = blockIdx.y, b = blockIdx.z;
    __shared__ __align__(16) float w[CSZ];
    __shared__ __align__(16) float xw[32][68];
    __shared__ __align__(16) float Bs[32][132];
    int tid = threadIdx.x;

    size_t hc = (((size_t)b*NH + h)*NCH + c)*CSZ;
    float dl = g_dAlast[((size_t)b*NH + h)*NCH + c];
    w[tid] = __expf(dl - g_dacs[hc + tid]) * g_dtsp[hc + tid];
    __syncthreads();

    int tx = tid & 15, ty = tid >> 4;   // tx -> n (8 each), ty -> p (4 each)
    float acc[4][8];
    #pragma unroll
    for (int i = 0; i < 4; i++)
        #pragma unroll
        for (int j = 0; j < 8; j++) acc[i][j] = 0.f;

    for (int s0 = 0; s0 < CSZ; s0 += 32) {
        for (int i = tid; i < 32*64; i += 256) {
            int s = i >> 6, p = i & 63;
            xw[s][p] = x[((size_t)(b*SEQ + c*CSZ + s0 + s)*NH + h)*HD + p] * w[s0 + s];
        }
        for (int i = tid; i < 32*128; i += 256) {
            int s = i >> 7, n = i & 127;
            Bs[s][n] = Bm[(size_t)(b*SEQ + c*CSZ + s0 + s)*DS + n];
        }
        __syncthreads();
        #pragma unroll
        for (int s = 0; s < 32; s++) {
            float4 xv = *(const float4*)&xw[s][ty*4];
            float4 b0 = *(const float4*)&Bs[s][tx*8];
            float4 b1 = *(const float4*)&Bs[s][tx*8+4];
            float xa[4] = {xv.x, xv.y, xv.z, xv.w};
            float ba[8] = {b0.x,b0.y,b0.z,b0.w,b1.x,b1.y,b1.z,b1.w};
            #pragma unroll
            for (int i = 0; i < 4; i++)
                #pragma unroll
                for (int j = 0; j < 8; j++)
                    acc[i][j] += xa[i]*ba[j];
        }
        __syncthreads();
    }
    float* sp = &g_states[(((size_t)b*NCH + c)*NH + h)*HD*DS];
    #pragma unroll
    for (int i = 0; i < 4; i++) {
        int p = ty*4 + i;
        float4 o0 = {acc[i][0],acc[i][1],acc[i][2],acc[i][3]};
        float4 o1 = {acc[i][4],acc[i][5],acc[i][6],acc[i][7]};
        *(float4*)&sp[(size_t)p*DS + tx*8]     = o0;
        *(float4*)&sp[(size_t)p*DS + tx*8 + 4] = o1;
    }
}

// ---------------- K4: CB[l,s] = sum_n C[l,n]*B[s,n]   (head independent) -----
__global__ void k_cb(const float* __restrict__ Cm, const float* __restrict__ Bm) {
    int t = blockIdx.x;                 // 16 tiles of 64x64
    int c = blockIdx.y, b = blockIdx.z;
    int lt = t >> 2, st = t & 3;
    __shared__ __align__(16) float Cs[64][33];
    __shared__ __align__(16) float Bs[64][33];
    int tid = threadIdx.x, tx = tid & 15, ty = tid >> 4;
    float acc[4][4];
    #pragma unroll
    for (int i = 0; i < 4; i++)
        #pragma unroll
        for (int j = 0; j < 4; j++) acc[i][j] = 0.f;

    for (int n0 = 0; n0 < DS; n0 += 32) {
        for (int i = tid; i < 64*32; i += 256) {
            int r = i >> 5, n = i & 31;
            Cs[r][n] = Cm[(size_t)(b*SEQ + c*CSZ + lt*64 + r)*DS + n0 + n];
            Bs[r][n] = Bm[(size_t)(b*SEQ + c*CSZ + st*64 + r)*DS + n0 + n];
        }
        __syncthreads();
        #pragma unroll
        for (int n = 0; n < 32; n++) {
            float ca[4], ba[4];
            #pragma unroll
            for (int i = 0; i < 4; i++) ca[i] = Cs[ty*4+i][n];
            #pragma unroll
            for (int j = 0; j < 4; j++) ba[j] = Bs[tx*4+j][n];
            #pragma unroll
            for (int i = 0; i < 4; i++)
                #pragma unroll
                for (int j = 0; j < 4; j++) acc[i][j] += ca[i]*ba[j];
        }
        __syncthreads();
    }
    float* cb = &g_CB[((size_t)b*NCH + c)*CSZ*CSZ];
    #pragma unroll
    for (int i = 0; i < 4; i++)
        #pragma unroll
        for (int j = 0; j < 4; j++)
            cb[(size_t)(lt*64 + ty*4 + i)*CSZ + st*64 + tx*4 + j] = acc[i][j];
}

// ---------------- K3: state passing across chunks + final_states -------------
__global__ void k_pass(float* __restrict__ finals) {
    int h = blockIdx.x % NH, b = blockIdx.x / NH;
    __shared__ float dec[NCH];
    if (threadIdx.x < NCH)
        dec[threadIdx.x] = __expf(g_dAlast[((size_t)b*NH + h)*NCH + threadIdx.x]);
    __syncthreads();
    for (int e = threadIdx.x; e < HD*DS; e += 256) {
        float run = 0.f;
        #pragma unroll
        for (int c = 0; c < NCH; c++) {
            size_t idx = (((size_t)b*NCH + c)*NH + h)*HD*DS + e;
            g_prev[idx] = run;
            run = run * dec[c] + g_states[idx];
        }
        if (finals) finals[((size_t)b*NH + h)*HD*DS + e] = run;
    }
}

// ---------------- K5: chunk_scan + inter-chunk + epilogue --------------------
__global__ void k_scan(const float* __restrict__ x, const float* __restrict__ z,
                       const float* __restrict__ Cm, const float* __restrict__ Dv,
                       float* __restrict__ out) {
    int h = blockIdx.x >> 1, ltb = blockIdx.x & 1;
    int c = blockIdx.y, b = blockIdx.z;
    int tid = threadIdx.x, tx = tid & 15, ty = tid >> 4; // tx -> p(4), ty -> l(8)
    int lbase = ltb * 128;

    __shared__ __align__(16) float Ms[128*33];
    __shared__ __align__(16) float xs[32][68];
    __shared__ float drow[128];
    __shared__ float el[128];

    size_t hcbase = (((size_t)b*NH + h)*NCH + c)*CSZ;
    const float* dacs_p = g_dacs + hcbase;
    const float* dtsp_p = g_dtsp + hcbase;
    if (tid < 128) {
        float d = dacs_p[lbase + tid];
        drow[tid] = d;
        el[tid] = __expf(d);
    }
    __syncthreads();

    float acc[8][4];
    #pragma unroll
    for (int i = 0; i < 8; i++)
        #pragma unroll
        for (int j = 0; j < 4; j++) acc[i][j] = 0.f;

    // ----- phase A: intra-chunk masked scores * x (causal tiles only) -----
    const float* cbp = &g_CB[((size_t)b*NCH + c)*CSZ*CSZ];
    for (int s0 = 0; s0 < lbase + 128; s0 += 32) {
        for (int i = tid; i < 128*32; i += 256) {
            int l = i >> 5, s = i & 31;
            int gl = lbase + l, gs = s0 + s;
            float v = 0.f;
            if (gl >= gs)
                v = cbp[(size_t)gl*CSZ + gs] * __expf(drow[l] - dacs_p[gs]) * dtsp_p[gs];
            Ms[l*33 + s] = v;
        }
        for (int i = tid; i < 32*64; i += 256) {
            int s = i >> 6, p = i & 63;
            xs[s][p] = x[((size_t)(b*SEQ + c*CSZ + s0 + s)*NH + h)*HD + p];
        }
        __syncthreads();
        #pragma unroll
        for (int s = 0; s < 32; s++) {
            float4 xv = *(const float4*)&xs[s][tx*4];
            #pragma unroll
            for (int i = 0; i < 8; i++) {
                float m = Ms[(ty*8 + i)*33 + s];
                acc[i][0] += m*xv.x; acc[i][1] += m*xv.y;
                acc[i][2] += m*xv.z; acc[i][3] += m*xv.w;
            }
        }
        __syncthreads();
    }

    // ----- phase B: inter-chunk  (C[l,:]*exp(dacs_l)) . prev[p,:]^T -----
    const float* prevp = &g_prev[(((size_t)b*NCH + c)*NH + h)*HD*DS];
    for (int n0 = 0; n0 < DS; n0 += 32) {
        for (int i = tid; i < 128*32; i += 256) {
            int l = i >> 5, n = i & 31;
            Ms[l*33 + n] = Cm[(size_t)(b*SEQ + c*CSZ + lbase + l)*DS + n0 + n] * el[l];
        }
        for (int i = tid; i < 64*32; i += 256) {
            int p = i >> 5, n = i & 31;
            xs[n][p] = prevp[(size_t)p*DS + n0 + n];   // transposed for float4 reads
        }
        __syncthreads();
        #pragma unroll
        for (int n = 0; n < 32; n++) {
            float4 pv = *(const float4*)&xs[n][tx*4];
            #pragma unroll
            for (int i = 0; i < 8; i++) {
                float m = Ms[(ty*8 + i)*33 + n];
                acc[i][0] += m*pv.x; acc[i][1] += m*pv.y;
                acc[i][2] += m*pv.z; acc[i][3] += m*pv.w;
            }
        }
        __syncthreads();
    }

    // ----- epilogue: + x*D, * silu(z) -----
    float Dh = Dv[h];
    #pragma unroll
    for (int i = 0; i < 8; i++) {
        int gl = c*CSZ + lbase + ty*8 + i;
        size_t base = ((size_t)(b*SEQ + gl)*NH + h)*HD + tx*4;
        float4 xv = *(const float4*)&x[base];
        float4 zv = *(const float4*)&z[base];
        float4 o;
        o.x = (acc[i][0] + xv.x*Dh) * (zv.x / (1.f + __expf(-zv.x)));
        o.y = (acc[i][1] + xv.y*Dh) * (zv.y / (1.f + __expf(-zv.y)));
        o.z = (acc[i][2] + xv.z*Dh) * (zv.z / (1.f + __expf(-zv.z)));
        o.w = (acc[i][3] + xv.w*Dh) * (zv.w / (1.f + __expf(-zv.w)));
        *(float4*)&out[base] = o;
    }
}

// ---------------- launch ------------------------------------------------------
extern "C" void kernel_launch(void* const* d_in, const int* in_sizes, int n_in,
                              void* d_out, int out_size) {
    const float* x   = (const float*)d_in[0];
    const float* dt  = (const float*)d_in[1];
    const float* A   = (const float*)d_in[2];
    const float* Bm  = (const float*)d_in[3];
    const float* Cm  = (const float*)d_in[4];
    const float* Dv  = (const float*)d_in[5];
    const float* z   = (const float*)d_in[6];
    const float* dtb = (const float*)d_in[7];
    float* out = (float*)d_out;

    const size_t OUT_MAIN = (size_t)BATCH*SEQ*NH*HD;   // 16,777,216
    float* finals = ((size_t)out_size > OUT_MAIN) ? out + OUT_MAIN : nullptr;

    k_dt   <<<BATCH*NH*NCH, CSZ>>>(dt, A, dtb);
    k_state<<<dim3(NH, NCH, BATCH), 256>>>(x, Bm);
    k_cb   <<<dim3(16, NCH, BATCH), 256>>>(Cm, Bm);
    k_pass <<<BATCH*NH, 256>>>(finals);
    k_scan <<<dim3(NH*2, NCH, BATCH), 256>>>(x, z, Cm, Dv, out);
}